// round 4
// baseline (speedup 1.0000x reference)
#include <cuda_runtime.h>

// ---------------------------------------------------------------------------
// VQ-VAE: nearest-code search + z_q gather + commitment loss + EMA update.
// Bit-exact emulation of the reference distance rounding:
//   u_k = fl( fl(z_sq - 2*dot_k) + e_sq_k );  key = fl(sqrt(max(u_k,0)))
//   argmin over key, first-index tie-break.
// z_sq / e_sq emulate XLA-CPU SIMD reduce of 8 (stride-4 chunk + halving tree):
//   v_j = s_j + s_{j+4};  sum = (v0+v2) + (v1+v3)
// ---------------------------------------------------------------------------

#define KCODES   512
#define DIM      8
#define HW       4096
#define NVEC     (64 * HW)
#define TPB      256
#define NBLK     512
#define CSTRIDE  4096
#define BSTRIDE  (DIM * HW)

#define OUT_ZQ   0
#define OUT_LOSS 2097152
#define OUT_CB   2097153
#define OUT_CS   (2097153 + 4096)
#define OUT_W    (2097153 + 4096 + 512)

// scratch (zero-initialized at module load; vq_finalize re-zeros each call)
__device__ float g_counts[KCODES];
__device__ float g_sums[KCODES * DIM];
__device__ float g_loss;

// -------- packed f32x2 helpers ---------------------------------------------
__device__ __forceinline__ unsigned long long pack2(float lo, float hi) {
    unsigned long long r;
    asm("mov.b64 %0, {%1, %2};" : "=l"(r) : "f"(lo), "f"(hi));
    return r;
}
__device__ __forceinline__ void unpack2(unsigned long long v, float& lo, float& hi) {
    asm("mov.b64 {%0, %1}, %2;" : "=f"(lo), "=f"(hi) : "l"(v));
}
__device__ __forceinline__ unsigned long long fma2(unsigned long long a,
                                                   unsigned long long b,
                                                   unsigned long long c) {
    unsigned long long d;
    asm("fma.rn.f32x2 %0, %1, %2, %3;" : "=l"(d) : "l"(a), "l"(b), "l"(c));
    return d;
}
__device__ __forceinline__ unsigned long long add2(unsigned long long a,
                                                   unsigned long long b) {
    unsigned long long d;
    asm("add.rn.f32x2 %0, %1, %2;" : "=l"(d) : "l"(a), "l"(b));
    return d;
}
__device__ __forceinline__ void lds2x64(unsigned addr, unsigned long long& a,
                                        unsigned long long& b) {
    asm volatile("ld.shared.v2.b64 {%0, %1}, [%2];"
                 : "=l"(a), "=l"(b) : "r"(addr));
}
__device__ __forceinline__ unsigned long long lds64(unsigned addr) {
    unsigned long long v;
    asm volatile("ld.shared.b64 %0, [%1];" : "=l"(v) : "r"(addr));
    return v;
}

// XLA-CPU SIMD sum of 8 squares: stride-4 chunk, then halving (butterfly) tree.
__device__ __forceinline__ float sumsq8(const float* x) {
    float s[DIM];
#pragma unroll
    for (int d = 0; d < DIM; d++) s[d] = __fmul_rn(x[d], x[d]);
    float v0 = __fadd_rn(s[0], s[4]);
    float v1 = __fadd_rn(s[1], s[5]);
    float v2 = __fadd_rn(s[2], s[6]);
    float v3 = __fadd_rn(s[3], s[7]);
    float w0 = __fadd_rn(v0, v2);
    float w1 = __fadd_rn(v1, v3);
    return __fadd_rn(w0, w1);
}

// ---------------------------------------------------------------------------
__global__ __launch_bounds__(TPB) void vq_main(const float* __restrict__ z,
                                               const float* __restrict__ cb,
                                               float* __restrict__ out) {
    // pair layout: sh_pair[kp*8 + d] = {e[2kp][d], e[2kp+1][d]}
    __shared__ __align__(16) float2 sh_pair[(KCODES / 2) * DIM];  // 16 KB
    __shared__ __align__(16) float  sh_e2[KCODES];                //  2 KB  e_sq[k]
    __shared__ float sh_cnt[KCODES];                              //  2 KB
    __shared__ float sh_sum[KCODES * DIM];                        // 16 KB
    __shared__ float sh_loss;

    const int tid = threadIdx.x;
    float* sp = (float*)sh_pair;

    for (int i = tid; i < KCODES * DIM; i += TPB) {
        int k = i >> 3, d = i & 7;
        sp[(((k >> 1) << 3) + d) * 2 + (k & 1)] = cb[i];
    }
    for (int k = tid; k < KCODES; k += TPB) {
        float e[DIM];
#pragma unroll
        for (int d = 0; d < DIM; d++) e[d] = cb[k * DIM + d];
        sh_e2[k] = sumsq8(e);
    }
    for (int i = tid; i < KCODES; i += TPB) sh_cnt[i] = 0.f;
    for (int i = tid; i < KCODES * DIM; i += TPB) sh_sum[i] = 0.f;
    if (tid == 0) sh_loss = 0.f;
    __syncthreads();

    const int v0i = blockIdx.x * (TPB * 2) + tid;
    const int v1i = v0i + TPB;
    const int b0 = v0i >> 12, n0 = v0i & 4095;
    const int b1 = v1i >> 12, n1 = v1i & 4095;
    const float* zp0 = z + b0 * BSTRIDE + n0;
    const float* zp1 = z + b1 * BSTRIDE + n1;

    float za[DIM], zb[DIM];
#pragma unroll
    for (int d = 0; d < DIM; d++) { za[d] = zp0[d * CSTRIDE]; zb[d] = zp1[d * CSTRIDE]; }

    const float zsqA = sumsq8(za);
    const float zsqB = sumsq8(zb);

    // packed -2*z (exact scaling -> acc == -2*dot with reference rounding)
    unsigned long long zza[DIM], zzb[DIM];
#pragma unroll
    for (int d = 0; d < DIM; d++) {
        float a = __fmul_rn(-2.0f, za[d]);
        float b = __fmul_rn(-2.0f, zb[d]);
        zza[d] = pack2(a, a);
        zzb[d] = pack2(b, b);
    }
    const unsigned long long zsq2A = pack2(zsqA, zsqA);
    const unsigned long long zsq2B = pack2(zsqB, zsqB);
    const unsigned long long zero2 = pack2(0.f, 0.f);

    const unsigned pbase = (unsigned)__cvta_generic_to_shared(sh_pair);
    const unsigned hbase = (unsigned)__cvta_generic_to_shared(sh_e2);

    float m1A = 3.4e38f, m2A = 3.4e38f, m1B = 3.4e38f, m2B = 3.4e38f;
    int i1A = 0, i1B = 0;

#pragma unroll 2
    for (int kp = 0; kp < KCODES / 2; kp++) {
        unsigned addr = pbase + kp * 64;
        unsigned long long e[DIM];
        lds2x64(addr,      e[0], e[1]);
        lds2x64(addr + 16, e[2], e[3]);
        lds2x64(addr + 32, e[4], e[5]);
        lds2x64(addr + 48, e[6], e[7]);
        unsigned long long ep = lds64(hbase + kp * 8);

        unsigned long long accA = zero2, accB = zero2;
#pragma unroll
        for (int i = 0; i < DIM; i++) {
            accA = fma2(zza[i], e[i], accA);
            accB = fma2(zzb[i], e[i], accB);
        }
        unsigned long long uA = add2(add2(zsq2A, accA), ep);
        unsigned long long uB = add2(add2(zsq2B, accB), ep);

        float u0, u1;
        unpack2(uA, u0, u1);
        {
            bool p = u0 < m1A;
            float t = fmaxf(m1A, u0);
            m2A = fminf(m2A, t);
            m1A = fminf(m1A, u0);
            i1A = p ? 2 * kp : i1A;
        }
        {
            bool p = u1 < m1A;
            float t = fmaxf(m1A, u1);
            m2A = fminf(m2A, t);
            m1A = fminf(m1A, u1);
            i1A = p ? 2 * kp + 1 : i1A;
        }
        unpack2(uB, u0, u1);
        {
            bool p = u0 < m1B;
            float t = fmaxf(m1B, u0);
            m2B = fminf(m2B, t);
            m1B = fminf(m1B, u0);
            i1B = p ? 2 * kp : i1B;
        }
        {
            bool p = u1 < m1B;
            float t = fmaxf(m1B, u1);
            m2B = fminf(m2B, t);
            m1B = fminf(m1B, u1);
            i1B = p ? 2 * kp + 1 : i1B;
        }
    }

    // ---- sqrt tie resolution (rare slow path) ----
    int biA = i1A, biB = i1B;
    {
        float q1 = __fsqrt_rn(fmaxf(m1A, 0.f));
        float q2 = __fsqrt_rn(fmaxf(m2A, 0.f));
        if (q2 == q1) {
            for (int k = 0; k < KCODES; k++) {
                float acc = 0.f;
#pragma unroll
                for (int d = 0; d < DIM; d++)
                    acc = __fmaf_rn(__fmul_rn(-2.0f, za[d]),
                                    sp[(((k >> 1) << 3) + d) * 2 + (k & 1)], acc);
                float u = __fadd_rn(__fadd_rn(zsqA, acc), sh_e2[k]);
                if (u <= m2A) {
                    float q = __fsqrt_rn(fmaxf(u, 0.f));
                    if (q == q1) { biA = k; break; }
                }
            }
        }
    }
    {
        float q1 = __fsqrt_rn(fmaxf(m1B, 0.f));
        float q2 = __fsqrt_rn(fmaxf(m2B, 0.f));
        if (q2 == q1) {
            for (int k = 0; k < KCODES; k++) {
                float acc = 0.f;
#pragma unroll
                for (int d = 0; d < DIM; d++)
                    acc = __fmaf_rn(__fmul_rn(-2.0f, zb[d]),
                                    sp[(((k >> 1) << 3) + d) * 2 + (k & 1)], acc);
                float u = __fadd_rn(__fadd_rn(zsqB, acc), sh_e2[k]);
                if (u <= m2B) {
                    float q = __fsqrt_rn(fmaxf(u, 0.f));
                    if (q == q1) { biB = k; break; }
                }
            }
        }
    }

    // ---- epilogue: z_q write, loss, histogram ----
    float lsum = 0.f;
    {
        int kp = biA >> 1, hf = biA & 1;
        float* outp = out + OUT_ZQ + b0 * BSTRIDE + n0;
#pragma unroll
        for (int d = 0; d < DIM; d++) {
            float e = sp[((kp << 3) + d) * 2 + hf];
            outp[d * CSTRIDE] = e;
            float df = e - za[d];
            lsum += df * df;
            atomicAdd(&sh_sum[biA * DIM + d], za[d]);
        }
        atomicAdd(&sh_cnt[biA], 1.f);
    }
    {
        int kp = biB >> 1, hf = biB & 1;
        float* outp = out + OUT_ZQ + b1 * BSTRIDE + n1;
#pragma unroll
        for (int d = 0; d < DIM; d++) {
            float e = sp[((kp << 3) + d) * 2 + hf];
            outp[d * CSTRIDE] = e;
            float df = e - zb[d];
            lsum += df * df;
            atomicAdd(&sh_sum[biB * DIM + d], zb[d]);
        }
        atomicAdd(&sh_cnt[biB], 1.f);
    }
    atomicAdd(&sh_loss, lsum);
    __syncthreads();

    for (int i = tid; i < KCODES; i += TPB) {
        float c = sh_cnt[i];
        if (c != 0.f) atomicAdd(&g_counts[i], c);
    }
    for (int i = tid; i < KCODES * DIM; i += TPB) {
        float s = sh_sum[i];
        if (s != 0.f) atomicAdd(&g_sums[i], s);
    }
    if (tid == 0) atomicAdd(&g_loss, sh_loss);
}

// ---------------------------------------------------------------------------
__global__ void vq_finalize(const float* __restrict__ ema_cs,
                            const float* __restrict__ ema_w,
                            float* __restrict__ out) {
    __shared__ float red[KCODES];
    const int k = threadIdx.x;

    float ncs = ema_cs[k] * 0.99f + g_counts[k] * 0.01f;
    red[k] = ncs;
    __syncthreads();
    for (int s = KCODES / 2; s > 0; s >>= 1) {
        if (k < s) red[k] += red[k + s];
        __syncthreads();
    }
    float n = red[0];
    float cs = (ncs + 1e-5f) / (n + KCODES * 1e-5f) * n;
    out[OUT_CS + k] = cs;

#pragma unroll
    for (int d = 0; d < DIM; d++) {
        float nw = ema_w[k * DIM + d] * 0.99f + g_sums[k * DIM + d] * 0.01f;
        out[OUT_W + k * DIM + d] = nw;
        out[OUT_CB + k * DIM + d] = nw / cs;
    }
    if (k == 0) out[OUT_LOSS] = g_loss * (1.0f / 2097152.0f);

    // reset scratch for the next graph replay (deterministic across calls)
    g_counts[k] = 0.f;
#pragma unroll
    for (int d = 0; d < DIM; d++) g_sums[k * DIM + d] = 0.f;
    if (k == 0) g_loss = 0.f;
}

// ---------------------------------------------------------------------------
extern "C" void kernel_launch(void* const* d_in, const int* in_sizes, int n_in,
                              void* d_out, int out_size) {
    const float* z      = (const float*)d_in[0];
    const float* cb     = (const float*)d_in[1];
    const float* ema_cs = (const float*)d_in[2];
    const float* ema_w  = (const float*)d_in[3];
    float* out = (float*)d_out;

    vq_main<<<NBLK, TPB>>>(z, cb, out);
    vq_finalize<<<1, KCODES>>>(ema_cs, ema_w, out);
}

// round 5
// speedup vs baseline: 1.0161x; 1.0161x over previous
#include <cuda_runtime.h>

// ---------------------------------------------------------------------------
// VQ-VAE: nearest-code search + z_q gather + commitment loss + EMA update.
// Bit-exact emulation of the reference distance rounding (DO NOT CHANGE):
//   u_k = fl( fl(z_sq - 2*dot_k) + e_sq_k );  key = fl(sqrt(max(u_k,0)))
//   argmin over key, first-index tie-break.
// z_sq / e_sq use XLA-CPU SIMD reduce-of-8 order (stride-4 chunk + halving
// tree):  v_j = s_j + s_{j+4};  sum = (v0+v2) + (v1+v3)
// Fully fused single kernel: search + histogram + last-block EMA finalize.
// ---------------------------------------------------------------------------

#define KCODES   512
#define DIM      8
#define HW       4096
#define NVEC     (64 * HW)
#define TPB      128
#define NBLK     (NVEC / (TPB * 2))   // 1024
#define CSTRIDE  4096
#define BSTRIDE  (DIM * HW)

#define OUT_ZQ   0
#define OUT_LOSS 2097152
#define OUT_CB   2097153
#define OUT_CS   (2097153 + 4096)
#define OUT_W    (2097153 + 4096 + 512)

// scratch (zero at module load; last block re-zeros each call for graph replay)
__device__ float g_counts[KCODES];
__device__ float g_sums[KCODES * DIM];
__device__ float g_loss;
__device__ int   g_ticket;

// -------- packed f32x2 helpers ---------------------------------------------
__device__ __forceinline__ unsigned long long pack2(float lo, float hi) {
    unsigned long long r;
    asm("mov.b64 %0, {%1, %2};" : "=l"(r) : "f"(lo), "f"(hi));
    return r;
}
__device__ __forceinline__ void unpack2(unsigned long long v, float& lo, float& hi) {
    asm("mov.b64 {%0, %1}, %2;" : "=f"(lo), "=f"(hi) : "l"(v));
}
__device__ __forceinline__ unsigned long long fma2(unsigned long long a,
                                                   unsigned long long b,
                                                   unsigned long long c) {
    unsigned long long d;
    asm("fma.rn.f32x2 %0, %1, %2, %3;" : "=l"(d) : "l"(a), "l"(b), "l"(c));
    return d;
}
__device__ __forceinline__ unsigned long long add2(unsigned long long a,
                                                   unsigned long long b) {
    unsigned long long d;
    asm("add.rn.f32x2 %0, %1, %2;" : "=l"(d) : "l"(a), "l"(b));
    return d;
}
__device__ __forceinline__ void lds2x64(unsigned addr, unsigned long long& a,
                                        unsigned long long& b) {
    asm volatile("ld.shared.v2.b64 {%0, %1}, [%2];"
                 : "=l"(a), "=l"(b) : "r"(addr));
}
__device__ __forceinline__ unsigned long long lds64(unsigned addr) {
    unsigned long long v;
    asm volatile("ld.shared.b64 %0, [%1];" : "=l"(v) : "r"(addr));
    return v;
}

// XLA-CPU SIMD sum of 8 squares: stride-4 chunk, then halving tree. (pinned)
__device__ __forceinline__ float sumsq8(const float* x) {
    float s[DIM];
#pragma unroll
    for (int d = 0; d < DIM; d++) s[d] = __fmul_rn(x[d], x[d]);
    float v0 = __fadd_rn(s[0], s[4]);
    float v1 = __fadd_rn(s[1], s[5]);
    float v2 = __fadd_rn(s[2], s[6]);
    float v3 = __fadd_rn(s[3], s[7]);
    return __fadd_rn(__fadd_rn(v0, v2), __fadd_rn(v1, v3));
}

// ---------------------------------------------------------------------------
__global__ __launch_bounds__(TPB, 5)
void vq_fused(const float* __restrict__ z, const float* __restrict__ cb,
              const float* __restrict__ ema_cs, const float* __restrict__ ema_w,
              float* __restrict__ out) {
    // pair layout: sh_pair[kp*8 + d] = {e[2kp][d], e[2kp+1][d]}
    __shared__ __align__(16) float2 sh_pair[(KCODES / 2) * DIM];  // 16 KB
    __shared__ __align__(16) float  sh_e2[KCODES];                //  2 KB
    __shared__ float sh_cnt[KCODES];                              //  2 KB
    __shared__ float sh_sum[KCODES * DIM];                        // 16 KB
    __shared__ float sh_loss;
    __shared__ int   sh_last;
    __shared__ float sh_n;

    const int tid = threadIdx.x;
    float* sp = (float*)sh_pair;

    for (int i = tid; i < KCODES * DIM; i += TPB) {
        int k = i >> 3, d = i & 7;
        sp[(((k >> 1) << 3) + d) * 2 + (k & 1)] = cb[i];
    }
    for (int k = tid; k < KCODES; k += TPB) {
        float e[DIM];
#pragma unroll
        for (int d = 0; d < DIM; d++) e[d] = cb[k * DIM + d];
        sh_e2[k] = sumsq8(e);
    }
    for (int i = tid; i < KCODES; i += TPB) sh_cnt[i] = 0.f;
    for (int i = tid; i < KCODES * DIM; i += TPB) sh_sum[i] = 0.f;
    if (tid == 0) sh_loss = 0.f;
    __syncthreads();

    const int v0i = blockIdx.x * (TPB * 2) + tid;
    const int v1i = v0i + TPB;
    const int b0 = v0i >> 12, n0 = v0i & 4095;
    const int b1 = v1i >> 12, n1 = v1i & 4095;
    const float* zp0 = z + b0 * BSTRIDE + n0;
    const float* zp1 = z + b1 * BSTRIDE + n1;

    // Load z, compute z_sq (pinned order), pack -2z; DON'T keep z in regs —
    // recover exactly in the epilogue as -0.5 * (-2z).
    unsigned long long zza[DIM], zzb[DIM];
    unsigned long long zsq2A, zsq2B;
    {
        float za[DIM], zb[DIM];
#pragma unroll
        for (int d = 0; d < DIM; d++) { za[d] = zp0[d * CSTRIDE]; zb[d] = zp1[d * CSTRIDE]; }
        float zsqA = sumsq8(za);
        float zsqB = sumsq8(zb);
#pragma unroll
        for (int d = 0; d < DIM; d++) {
            float a = __fmul_rn(-2.0f, za[d]);   // exact
            float b = __fmul_rn(-2.0f, zb[d]);
            zza[d] = pack2(a, a);
            zzb[d] = pack2(b, b);
        }
        zsq2A = pack2(zsqA, zsqA);
        zsq2B = pack2(zsqB, zsqB);
    }
    const unsigned long long zero2 = pack2(0.f, 0.f);

    const unsigned pbase = (unsigned)__cvta_generic_to_shared(sh_pair);
    const unsigned hbase = (unsigned)__cvta_generic_to_shared(sh_e2);

    float m1A = 3.4e38f, m2A = 3.4e38f, m1B = 3.4e38f, m2B = 3.4e38f;
    int i1A = 0, i1B = 0;

    for (int kp = 0; kp < KCODES / 2; kp++) {
        unsigned addr = pbase + kp * 64;
        unsigned long long e[DIM];
        lds2x64(addr,      e[0], e[1]);
        lds2x64(addr + 16, e[2], e[3]);
        lds2x64(addr + 32, e[4], e[5]);
        lds2x64(addr + 48, e[6], e[7]);
        unsigned long long ep = lds64(hbase + kp * 8);

        unsigned long long accA = zero2, accB = zero2;
#pragma unroll
        for (int i = 0; i < DIM; i++) {
            accA = fma2(zza[i], e[i], accA);
            accB = fma2(zzb[i], e[i], accB);
        }
        unsigned long long uA = add2(add2(zsq2A, accA), ep);
        unsigned long long uB = add2(add2(zsq2B, accB), ep);

        float u0, u1;
        unpack2(uA, u0, u1);
        {
            bool p = u0 < m1A;
            float t = fmaxf(m1A, u0);
            m2A = fminf(m2A, t);
            m1A = fminf(m1A, u0);
            i1A = p ? 2 * kp : i1A;
        }
        {
            bool p = u1 < m1A;
            float t = fmaxf(m1A, u1);
            m2A = fminf(m2A, t);
            m1A = fminf(m1A, u1);
            i1A = p ? 2 * kp + 1 : i1A;
        }
        unpack2(uB, u0, u1);
        {
            bool p = u0 < m1B;
            float t = fmaxf(m1B, u0);
            m2B = fminf(m2B, t);
            m1B = fminf(m1B, u0);
            i1B = p ? 2 * kp : i1B;
        }
        {
            bool p = u1 < m1B;
            float t = fmaxf(m1B, u1);
            m2B = fminf(m2B, t);
            m1B = fminf(m1B, u1);
            i1B = p ? 2 * kp + 1 : i1B;
        }
    }

    // recover z exactly: z[d] = -0.5 * (-2 z[d])
    float za[DIM], zb[DIM];
#pragma unroll
    for (int d = 0; d < DIM; d++) {
        float lo, hi;
        unpack2(zza[d], lo, hi);
        za[d] = -0.5f * lo;
        unpack2(zzb[d], lo, hi);
        zb[d] = -0.5f * lo;
    }
    float zsqA, zsqB, dum;
    unpack2(zsq2A, zsqA, dum);
    unpack2(zsq2B, zsqB, dum);

    // ---- sqrt tie resolution (rare): first index whose KEY equals min key.
    int biA = i1A, biB = i1B;
    if (__fsqrt_rn(fmaxf(m2A, 0.f)) == __fsqrt_rn(fmaxf(m1A, 0.f))) {
        float q1 = __fsqrt_rn(fmaxf(m1A, 0.f));
        for (int k = 0; k < KCODES; k++) {
            float acc = 0.f;
#pragma unroll
            for (int d = 0; d < DIM; d++)
                acc = __fmaf_rn(__fmul_rn(-2.0f, za[d]),
                                sp[(((k >> 1) << 3) + d) * 2 + (k & 1)], acc);
            float u = __fadd_rn(__fadd_rn(zsqA, acc), sh_e2[k]);
            if (__fsqrt_rn(fmaxf(u, 0.f)) == q1) { biA = k; break; }
        }
    }
    if (__fsqrt_rn(fmaxf(m2B, 0.f)) == __fsqrt_rn(fmaxf(m1B, 0.f))) {
        float q1 = __fsqrt_rn(fmaxf(m1B, 0.f));
        for (int k = 0; k < KCODES; k++) {
            float acc = 0.f;
#pragma unroll
            for (int d = 0; d < DIM; d++)
                acc = __fmaf_rn(__fmul_rn(-2.0f, zb[d]),
                                sp[(((k >> 1) << 3) + d) * 2 + (k & 1)], acc);
            float u = __fadd_rn(__fadd_rn(zsqB, acc), sh_e2[k]);
            if (__fsqrt_rn(fmaxf(u, 0.f)) == q1) { biB = k; break; }
        }
    }

    // ---- epilogue: z_q write, loss, block histogram ----
    float lsum = 0.f;
    {
        int kp = biA >> 1, hf = biA & 1;
        float* outp = out + OUT_ZQ + b0 * BSTRIDE + n0;
#pragma unroll
        for (int d = 0; d < DIM; d++) {
            float e = sp[((kp << 3) + d) * 2 + hf];
            outp[d * CSTRIDE] = e;
            float df = e - za[d];
            lsum += df * df;
            atomicAdd(&sh_sum[biA * DIM + d], za[d]);
        }
        atomicAdd(&sh_cnt[biA], 1.f);
    }
    {
        int kp = biB >> 1, hf = biB & 1;
        float* outp = out + OUT_ZQ + b1 * BSTRIDE + n1;
#pragma unroll
        for (int d = 0; d < DIM; d++) {
            float e = sp[((kp << 3) + d) * 2 + hf];
            outp[d * CSTRIDE] = e;
            float df = e - zb[d];
            lsum += df * df;
            atomicAdd(&sh_sum[biB * DIM + d], zb[d]);
        }
        atomicAdd(&sh_cnt[biB], 1.f);
    }
    atomicAdd(&sh_loss, lsum);
    __syncthreads();

    // ---- flush to global ----
    for (int i = tid; i < KCODES; i += TPB) {
        float c = sh_cnt[i];
        if (c != 0.f) atomicAdd(&g_counts[i], c);
    }
    for (int i = tid; i < KCODES * DIM; i += TPB) {
        float s = sh_sum[i];
        if (s != 0.f) atomicAdd(&g_sums[i], s);
    }
    if (tid == 0) atomicAdd(&g_loss, sh_loss);

    // ---- last-block EMA finalize ----
    __threadfence();
    __syncthreads();
    if (tid == 0) sh_last = (atomicAdd(&g_ticket, 1) == NBLK - 1);
    __syncthreads();
    if (!sh_last) return;

    // reuse sh_cnt as ncs staging
    float ncs_l[4];
#pragma unroll
    for (int j = 0; j < 4; j++) {
        int k = tid + j * TPB;
        float ncs = ema_cs[k] * 0.99f + __ldcg(&g_counts[k]) * 0.01f;
        ncs_l[j] = ncs;
        sh_cnt[k] = ncs;
    }
    __syncthreads();
    // n = sum of all 512 ncs (deterministic tree)
    if (tid < 64) {
        float s = 0.f;
#pragma unroll
        for (int j = 0; j < 8; j++) s += sh_cnt[tid * 8 + j];
        sh_sum[tid] = s;   // reuse sh_sum scratch
    }
    __syncthreads();
    if (tid == 0) {
        float s = 0.f;
        for (int i = 0; i < 64; i++) s += sh_sum[i];
        sh_n = s;
        out[OUT_LOSS] = __ldcg(&g_loss) * (1.0f / 2097152.0f);
        g_loss = 0.f;
        g_ticket = 0;
    }
    __syncthreads();
    const float n = sh_n;
#pragma unroll
    for (int j = 0; j < 4; j++) {
        int k = tid + j * TPB;
        float cs = (ncs_l[j] + 1e-5f) / (n + KCODES * 1e-5f) * n;
        out[OUT_CS + k] = cs;
        float inv = 1.0f / cs;
#pragma unroll
        for (int d = 0; d < DIM; d++) {
            float nw = ema_w[k * DIM + d] * 0.99f + __ldcg(&g_sums[k * DIM + d]) * 0.01f;
            out[OUT_W + k * DIM + d] = nw;
            out[OUT_CB + k * DIM + d] = nw * inv;
            g_sums[k * DIM + d] = 0.f;   // reset for next replay
        }
        g_counts[k] = 0.f;
    }
}

// ---------------------------------------------------------------------------
extern "C" void kernel_launch(void* const* d_in, const int* in_sizes, int n_in,
                              void* d_out, int out_size) {
    const float* z      = (const float*)d_in[0];
    const float* cb     = (const float*)d_in[1];
    const float* ema_cs = (const float*)d_in[2];
    const float* ema_w  = (const float*)d_in[3];
    float* out = (float*)d_out;

    vq_fused<<<NBLK, TPB>>>(z, cb, ema_cs, ema_w, out);
}